// round 17
// baseline (speedup 1.0000x reference)
#include <cuda_runtime.h>
#include <cuda_fp16.h>
#include <cstdint>

#define NN 100000
#define NE 1600000
#define IN_CH 256
#define HID 128
#define OUT_CH 64

#define SCH 1024                       // elements per scan chunk
#define NCHK ((NN + SCH - 1) / SCH)    // 98 chunks

// Scratch (device globals: allocation-free per harness rules)
__device__ __align__(16) __half g_h[(size_t)NN * HID];   // 25.6 MB (fp16)
__device__ int   g_deg[NN];
__device__ int   g_row_off[NN + 1];
__device__ int   g_cursor[NN];
__device__ int   g_csr_src[NE];
__device__ int   g_part[NCHK];
__device__ __align__(16) float g_W12[HID * OUT_CH];      // W1 @ W2, [k][o]

// ---------------------------------------------------------------------------
// prep: W12 = W1 @ W2  (fp32; re-association error ~1e-7 rel; proven R11/R15)
// ---------------------------------------------------------------------------
__global__ void prep_w12(const float* __restrict__ W1, const float* __restrict__ W2)
{
    int i = blockIdx.x * blockDim.x + threadIdx.x;   // HID*OUT_CH = 8192
    if (i >= HID * OUT_CH) return;
    int k = i >> 6, o = i & 63;
    float s = 0.f;
#pragma unroll 8
    for (int j = 0; j < HID; j++) s += W1[k * HID + j] * W2[j * OUT_CH + o];
    g_W12[i] = s;
}

// ---------------------------------------------------------------------------
// SGEMM (GEMM1): h[M,128] = x[M,256] @ Wg, fp16 output. BM=128, BK=16.
// ---------------------------------------------------------------------------
template <int K, int N>
__global__ void __launch_bounds__(256) sgemm_h_kernel(const float* __restrict__ A,
                                                      const float* __restrict__ B,
                                                      __half* __restrict__ Ch, int M)
{
    constexpr int BM = 128, BN = N, BK = 16;
    constexpr int TM = 8, TN = BN / 16;          // 8
    __shared__ float As[BK][BM];
    __shared__ float Bs[BK][BN];

    const int tid = threadIdx.x;
    const int tx = tid & 15;
    const int ty = tid >> 4;
    const int row0 = blockIdx.x * BM;

    float acc[TM][TN];
#pragma unroll
    for (int i = 0; i < TM; i++)
#pragma unroll
        for (int j = 0; j < TN; j++) acc[i][j] = 0.f;

    const int ar = tid >> 1;
    const int ak = (tid & 1) * 8;

    for (int k0 = 0; k0 < K; k0 += BK) {
        {
            int gr = row0 + ar;
            float4 v0 = make_float4(0.f, 0.f, 0.f, 0.f), v1 = v0;
            if (gr < M) {
                const float* gp = &A[(size_t)gr * K + k0 + ak];
                v0 = *reinterpret_cast<const float4*>(gp);
                v1 = *reinterpret_cast<const float4*>(gp + 4);
            }
            As[ak + 0][ar] = v0.x; As[ak + 1][ar] = v0.y;
            As[ak + 2][ar] = v0.z; As[ak + 3][ar] = v0.w;
            As[ak + 4][ar] = v1.x; As[ak + 5][ar] = v1.y;
            As[ak + 6][ar] = v1.z; As[ak + 7][ar] = v1.w;
        }
#pragma unroll
        for (int q = 0; q < (BK * BN) / 1024; q++) {
            int idx = (tid + q * 256) * 4;
            int kk = idx / BN, c = idx % BN;
            *reinterpret_cast<float4*>(&Bs[kk][c]) =
                *reinterpret_cast<const float4*>(&B[(size_t)(k0 + kk) * N + c]);
        }
        __syncthreads();

#pragma unroll
        for (int kk = 0; kk < BK; kk++) {
            float a[TM], b[TN];
            float4 a0 = *reinterpret_cast<const float4*>(&As[kk][ty * TM]);
            float4 a1 = *reinterpret_cast<const float4*>(&As[kk][ty * TM + 4]);
            a[0]=a0.x; a[1]=a0.y; a[2]=a0.z; a[3]=a0.w;
            a[4]=a1.x; a[5]=a1.y; a[6]=a1.z; a[7]=a1.w;
            float4 b0 = *reinterpret_cast<const float4*>(&Bs[kk][tx * TN]);
            float4 b1 = *reinterpret_cast<const float4*>(&Bs[kk][tx * TN + 4]);
            b[0]=b0.x; b[1]=b0.y; b[2]=b0.z; b[3]=b0.w;
            b[4]=b1.x; b[5]=b1.y; b[6]=b1.z; b[7]=b1.w;
#pragma unroll
            for (int i = 0; i < TM; i++)
#pragma unroll
                for (int j = 0; j < TN; j++)
                    acc[i][j] = fmaf(a[i], b[j], acc[i][j]);
        }
        __syncthreads();
    }

#pragma unroll
    for (int i = 0; i < TM; i++) {
        int gr = row0 + ty * TM + i;
        if (gr < M) {
            __half2 p0 = __floats2half2_rn(acc[i][0], acc[i][1]);
            __half2 p1 = __floats2half2_rn(acc[i][2], acc[i][3]);
            __half2 p2 = __floats2half2_rn(acc[i][4], acc[i][5]);
            __half2 p3 = __floats2half2_rn(acc[i][6], acc[i][7]);
            uint4 pk;
            pk.x = *reinterpret_cast<uint32_t*>(&p0);
            pk.y = *reinterpret_cast<uint32_t*>(&p1);
            pk.z = *reinterpret_cast<uint32_t*>(&p2);
            pk.w = *reinterpret_cast<uint32_t*>(&p3);
            *reinterpret_cast<uint4*>(&Ch[(size_t)gr * N + tx * TN]) = pk;
        }
    }
}

// ---------------------------------------------------------------------------
// CSR build: histogram -> 3-phase parallel exclusive scan -> cursor fill
// ---------------------------------------------------------------------------
__global__ void hist_kernel(const int* __restrict__ dst)
{
    int stride = gridDim.x * blockDim.x;
    for (int e = blockIdx.x * blockDim.x + threadIdx.x; e < NE; e += stride)
        atomicAdd(&g_deg[dst[e]], 1);
}

__global__ void __launch_bounds__(256) scan_partial_kernel()
{
    __shared__ int red[8];
    int b = blockIdx.x, t = threadIdx.x;
    int base = b * SCH;
    int sum = 0;
#pragma unroll
    for (int q = 0; q < SCH / 256; q++) {
        int i = base + q * 256 + t;
        if (i < NN) sum += g_deg[i];
    }
    for (int o = 16; o > 0; o >>= 1) sum += __shfl_down_sync(0xffffffffu, sum, o);
    if ((t & 31) == 0) red[t >> 5] = sum;
    __syncthreads();
    if (t < 8) {
        int v = red[t];
        for (int o = 4; o > 0; o >>= 1) v += __shfl_down_sync(0xffu, v, o);
        if (t == 0) g_part[b] = v;
    }
}

__global__ void __launch_bounds__(128) scan_chunks_kernel()
{
    __shared__ int s[128];
    int t = threadIdx.x;
    int v = (t < NCHK) ? g_part[t] : 0;
    s[t] = v;
    __syncthreads();
#pragma unroll
    for (int o = 1; o < 128; o <<= 1) {
        int u = (t >= o) ? s[t - o] : 0;
        __syncthreads();
        s[t] += u;
        __syncthreads();
    }
    if (t < NCHK) g_part[t] = s[t] - v;
    if (t == 127) g_row_off[NN] = s[127];
}

__global__ void __launch_bounds__(256) scan_write_kernel()
{
    __shared__ int s[256];
    int b = blockIdx.x, t = threadIdx.x;
    int i0 = b * SCH + t * 4;

    int4 d = make_int4(0, 0, 0, 0);
    if (i0 < NN) d = *reinterpret_cast<const int4*>(&g_deg[i0]);  // NN % 4 == 0
    int tsum = d.x + d.y + d.z + d.w;

    s[t] = tsum;
    __syncthreads();
#pragma unroll
    for (int o = 1; o < 256; o <<= 1) {
        int u = (t >= o) ? s[t - o] : 0;
        __syncthreads();
        s[t] += u;
        __syncthreads();
    }
    int base = g_part[b] + s[t] - tsum;

    if (i0 < NN) {
        int4 ro, cu;
        ro.x = base;             cu.x = ro.x;
        ro.y = ro.x + d.x;       cu.y = ro.y;
        ro.z = ro.y + d.y;       cu.z = ro.z;
        ro.w = ro.z + d.z;       cu.w = ro.w;
        *reinterpret_cast<int4*>(&g_row_off[i0]) = ro;
        *reinterpret_cast<int4*>(&g_cursor[i0]) = cu;
    }
}

__global__ void fill_kernel(const int* __restrict__ src, const int* __restrict__ dst)
{
    int stride = gridDim.x * blockDim.x;
    for (int e = blockIdx.x * blockDim.x + threadIdx.x; e < NE; e += stride) {
        int pos = atomicAdd(&g_cursor[dst[e]], 1);
        g_csr_src[pos] = src[e];
    }
}

// ---------------------------------------------------------------------------
// Fused agg + MLP kernel: per 128-row tile,
//   phase 1: out1 rows via CSR gather (fp16 h, fp32 accum) -> gmem + smem As4
//   phase 2: out2 = A @ W1   (from smem A)
//   phase 3: out3 = A @ W12  (from smem A)
// As4 layout: [kq][row], kq = channel quad (float4), pitch RPQ=129 (bank-clean).
// ---------------------------------------------------------------------------
__global__ void __launch_bounds__(256, 2) fused_mlp_kernel(
    const float* __restrict__ bias,
    const float* __restrict__ W1,
    float* __restrict__ out1, float* __restrict__ out2,
    float* __restrict__ out3, int M)
{
    constexpr int RPQ = 129;
    extern __shared__ float4 sm4[];
    float4* As4 = sm4;                                       // 32 * RPQ float4
    float*  Bs  = reinterpret_cast<float*>(sm4 + 32 * RPQ);  // 16*128 floats

    const int tid = threadIdx.x;
    const int wid = tid >> 5, lane = tid & 31;
    const int tx = tid & 15, ty = tid >> 4;
    const int row0 = blockIdx.x * 128;

    // ---- Phase 1: aggregation for this tile's 128 nodes ----
    {
        const uint2* h2 = reinterpret_cast<const uint2*>(g_h);
        float4 bv = reinterpret_cast<const float4*>(bias)[lane];
        for (int q = 0; q < 16; q++) {
            int r = wid * 16 + q;
            int node = row0 + r;
            float4 acc0 = make_float4(0.f, 0.f, 0.f, 0.f);
            if (node < M) {
                float4 acc1 = make_float4(0.f, 0.f, 0.f, 0.f);
                int s = g_row_off[node];
                int e = g_row_off[node + 1];
                int i = s;
                for (; i + 1 < e; i += 2) {
                    int s0 = g_csr_src[i];
                    int s1 = g_csr_src[i + 1];
                    uint2 u0 = h2[(size_t)s0 * 32 + lane];
                    uint2 u1 = h2[(size_t)s1 * 32 + lane];
                    float2 a = __half22float2(*reinterpret_cast<__half2*>(&u0.x));
                    float2 b = __half22float2(*reinterpret_cast<__half2*>(&u0.y));
                    float2 c = __half22float2(*reinterpret_cast<__half2*>(&u1.x));
                    float2 d = __half22float2(*reinterpret_cast<__half2*>(&u1.y));
                    acc0.x += a.x; acc0.y += a.y; acc0.z += b.x; acc0.w += b.y;
                    acc1.x += c.x; acc1.y += c.y; acc1.z += d.x; acc1.w += d.y;
                }
                if (i < e) {
                    int s0 = g_csr_src[i];
                    uint2 u0 = h2[(size_t)s0 * 32 + lane];
                    float2 a = __half22float2(*reinterpret_cast<__half2*>(&u0.x));
                    float2 b = __half22float2(*reinterpret_cast<__half2*>(&u0.y));
                    acc0.x += a.x; acc0.y += a.y; acc0.z += b.x; acc0.w += b.y;
                }
                acc0.x += acc1.x + bv.x; acc0.y += acc1.y + bv.y;
                acc0.z += acc1.z + bv.z; acc0.w += acc1.w + bv.w;
                reinterpret_cast<float4*>(out1)[(size_t)node * 32 + lane] = acc0;
            }
            As4[lane * RPQ + r] = acc0;    // channel-quad-major A tile
        }
    }
    __syncthreads();

    // ---- Phase 2: out2 = A @ W1  (BN=128, TN=8) ----
    {
        float acc[8][8];
#pragma unroll
        for (int i = 0; i < 8; i++)
#pragma unroll
            for (int j = 0; j < 8; j++) acc[i][j] = 0.f;

        for (int k0 = 0; k0 < 128; k0 += 16) {
#pragma unroll
            for (int q2 = 0; q2 < 2; q2++) {
                int idx = (tid + q2 * 256) * 4;
                int kk = idx >> 7, c = idx & 127;
                *reinterpret_cast<float4*>(&Bs[kk * 128 + c]) =
                    *reinterpret_cast<const float4*>(&W1[(size_t)(k0 + kk) * 128 + c]);
            }
            __syncthreads();

#pragma unroll
            for (int g = 0; g < 4; g++) {
                int kq = (k0 >> 2) + g;
                float4 a4[8];
#pragma unroll
                for (int i = 0; i < 8; i++)
                    a4[i] = As4[kq * RPQ + ty * 8 + i];
#pragma unroll
                for (int c = 0; c < 4; c++) {
                    int kk = g * 4 + c;
                    float b[8];
                    float4 b0 = *reinterpret_cast<const float4*>(&Bs[kk * 128 + tx * 8]);
                    float4 b1 = *reinterpret_cast<const float4*>(&Bs[kk * 128 + tx * 8 + 4]);
                    b[0]=b0.x; b[1]=b0.y; b[2]=b0.z; b[3]=b0.w;
                    b[4]=b1.x; b[5]=b1.y; b[6]=b1.z; b[7]=b1.w;
#pragma unroll
                    for (int i = 0; i < 8; i++) {
                        float av = (c == 0) ? a4[i].x : (c == 1) ? a4[i].y
                                 : (c == 2) ? a4[i].z : a4[i].w;
#pragma unroll
                        for (int j = 0; j < 8; j++)
                            acc[i][j] = fmaf(av, b[j], acc[i][j]);
                    }
                }
            }
            __syncthreads();
        }

#pragma unroll
        for (int i = 0; i < 8; i++) {
            int gr = row0 + ty * 8 + i;
            if (gr < M) {
                float* p2 = &out2[(size_t)gr * 128 + tx * 8];
                *reinterpret_cast<float4*>(p2) =
                    make_float4(acc[i][0], acc[i][1], acc[i][2], acc[i][3]);
                *reinterpret_cast<float4*>(p2 + 4) =
                    make_float4(acc[i][4], acc[i][5], acc[i][6], acc[i][7]);
            }
        }
    }

    // ---- Phase 3: out3 = A @ W12  (BN=64, TN=4) ----
    {
        float acc[8][4];
#pragma unroll
        for (int i = 0; i < 8; i++)
#pragma unroll
            for (int j = 0; j < 4; j++) acc[i][j] = 0.f;

        for (int k0 = 0; k0 < 128; k0 += 16) {
            __syncthreads();   // all threads done reading previous Bs contents
            {
                int idx = tid * 4;
                int kk = idx >> 6, c = idx & 63;
                *reinterpret_cast<float4*>(&Bs[kk * 64 + c]) =
                    *reinterpret_cast<const float4*>(&g_W12[(size_t)(k0 + kk) * 64 + c]);
            }
            __syncthreads();

#pragma unroll
            for (int g = 0; g < 4; g++) {
                int kq = (k0 >> 2) + g;
                float4 a4[8];
#pragma unroll
                for (int i = 0; i < 8; i++)
                    a4[i] = As4[kq * RPQ + ty * 8 + i];
#pragma unroll
                for (int c = 0; c < 4; c++) {
                    int kk = g * 4 + c;
                    float4 b0 = *reinterpret_cast<const float4*>(&Bs[kk * 64 + tx * 4]);
                    float b[4] = {b0.x, b0.y, b0.z, b0.w};
#pragma unroll
                    for (int i = 0; i < 8; i++) {
                        float av = (c == 0) ? a4[i].x : (c == 1) ? a4[i].y
                                 : (c == 2) ? a4[i].z : a4[i].w;
#pragma unroll
                        for (int j = 0; j < 4; j++)
                            acc[i][j] = fmaf(av, b[j], acc[i][j]);
                    }
                }
            }
        }

#pragma unroll
        for (int i = 0; i < 8; i++) {
            int gr = row0 + ty * 8 + i;
            if (gr < M)
                *reinterpret_cast<float4*>(&out3[(size_t)gr * 64 + tx * 4]) =
                    make_float4(acc[i][0], acc[i][1], acc[i][2], acc[i][3]);
        }
    }
}

// ---------------------------------------------------------------------------
extern "C" void kernel_launch(void* const* d_in, const int* in_sizes, int n_in,
                              void* d_out, int out_size)
{
    const float* x   = (const float*)d_in[0];
    const int* edge  = (const int*)d_in[1];
    const float* Wg  = (const float*)d_in[2];
    const float* bg  = (const float*)d_in[3];
    const float* W1  = (const float*)d_in[4];
    const float* W2  = (const float*)d_in[5];
    const int* src = edge;
    const int* dst = edge + NE;

    float* out  = (float*)d_out;
    float* out1 = out;                                  // [NN, HID]
    float* out2 = out1 + (size_t)NN * HID;              // [NN, HID]
    float* out3 = out2 + (size_t)NN * HID;              // [NN, OUT_CH]

    __half* h = nullptr;
    cudaGetSymbolAddress((void**)&h, g_h);
    int* degPtr = nullptr;
    cudaGetSymbolAddress((void**)&degPtr, g_deg);

    // one-time stream + events (same DAG captured every call)
    static cudaStream_t s_side = nullptr;
    static cudaEvent_t ev_fork = nullptr, ev_join = nullptr;
    static bool attr_set = false;
    const int FUSED_SMEM = 32 * 129 * 16 + 16 * 128 * 4;   // 74240 B
    if (s_side == nullptr) {
        cudaStreamCreateWithFlags(&s_side, cudaStreamNonBlocking);
        cudaEventCreateWithFlags(&ev_fork, cudaEventDisableTiming);
        cudaEventCreateWithFlags(&ev_join, cudaEventDisableTiming);
    }
    if (!attr_set) {
        cudaFuncSetAttribute(fused_mlp_kernel,
                             cudaFuncAttributeMaxDynamicSharedMemorySize, FUSED_SMEM);
        attr_set = true;
    }

    const int M = NN;
    const int MBLK = (M + 127) / 128;   // 782

    // fork: CSR build + W12 prep on side stream, concurrent with GEMM1
    cudaEventRecord(ev_fork, 0);
    cudaStreamWaitEvent(s_side, ev_fork, 0);

    prep_w12<<<(HID * OUT_CH + 255) / 256, 256, 0, s_side>>>(W1, W2);
    cudaMemsetAsync(degPtr, 0, NN * sizeof(int), s_side);
    hist_kernel<<<1024, 256, 0, s_side>>>(dst);
    scan_partial_kernel<<<NCHK, 256, 0, s_side>>>();
    scan_chunks_kernel<<<1, 128, 0, s_side>>>();
    scan_write_kernel<<<NCHK, 256, 0, s_side>>>();
    fill_kernel<<<1024, 256, 0, s_side>>>(src, dst);
    cudaEventRecord(ev_join, s_side);

    // main stream: GEMM1 (independent of CSR build)
    sgemm_h_kernel<IN_CH, HID><<<MBLK, 256>>>(x, Wg, h, M);

    // join: fused kernel needs GEMM1 (h), CSR (row_off/csr_src) and W12
    cudaStreamWaitEvent(0, ev_join, 0);

    // fused agg + MLP (out1, out2, out3 in one pass)
    fused_mlp_kernel<<<MBLK, 256, FUSED_SMEM>>>(bg, W1, out1, out2, out3, M);
}